// round 7
// baseline (speedup 1.0000x reference)
#include <cuda_runtime.h>
#include <cstdint>

// Problem constants (fixed by the dataset)
#define BVAL   2048
#define TVAL   2048
#define HVAL   64
#define BTILE  8                    // max batches per CTA (heavy CTA)
#define THREADS 128                 // 4 warps per CTA
#define NSM    148
#define GRID   (2 * NSM)            // 296 CTAs -> exactly 2 per SM

// ---------- packed f32x2 helpers (Blackwell) ----------
__device__ __forceinline__ unsigned long long ffma2(unsigned long long a,
                                                    unsigned long long b,
                                                    unsigned long long c) {
    unsigned long long d;
    asm("fma.rn.f32x2 %0, %1, %2, %3;" : "=l"(d) : "l"(a), "l"(b), "l"(c));
    return d;
}
__device__ __forceinline__ unsigned long long fadd2(unsigned long long a,
                                                    unsigned long long b) {
    unsigned long long d;
    asm("add.rn.f32x2 %0, %1, %2;" : "=l"(d) : "l"(a), "l"(b));
    return d;
}
__device__ __forceinline__ float lo32(unsigned long long v) {
    return __uint_as_float((unsigned)v);
}
__device__ __forceinline__ float hi32(unsigned long long v) {
    return __uint_as_float((unsigned)(v >> 32));
}
__device__ __forceinline__ unsigned long long pack2(float lo, float hi) {
    return (unsigned long long)__float_as_uint(lo) |
           ((unsigned long long)__float_as_uint(hi) << 32);
}

// tanh(s) = 1 - 2/(e^{2s}+1): 5 ops, no clamp (ex2->inf -> rcp->0 -> 1 exact;
// ex2->0 -> rcp(1)=1 -> -1 exact). rel err ~1e-7 per step.
__device__ __forceinline__ float fast_tanh(float s) {
    float z = s * 2.885390082f;                 // 2*log2(e)*s
    float p; asm("ex2.approx.f32 %0, %1;" : "=f"(p) : "f"(z));
    float r; asm("rcp.approx.f32 %0, %1;" : "=f"(r) : "f"(p + 1.0f));
    return fmaf(-2.0f, r, 1.0f);
}

// The full time loop for a warp owning NB batches. Warp-private: only
// __syncwarp between steps. Each lane owns rows j0=lane and j1=lane+32.
template<int NB>
__device__ __forceinline__ void run_loop(
    const float* __restrict__ x, const float* __restrict__ W_ih,
    const float* __restrict__ W_hh, const float* __restrict__ b_ih,
    const float* __restrict__ b_hh, const float* __restrict__ W_fc,
    const float* __restrict__ b_fc, float* __restrict__ out,
    float (&hbuf)[2][BTILE][HVAL], int lane, int lslot, int gbatch)
{
    const int j0 = lane;
    const int j1 = lane + 32;

    // W_hh rows j0, j1: k-packed u64 (128 regs, shared across NB batches)
    unsigned long long wA[HVAL / 2], wB[HVAL / 2];
    {
        const unsigned long long* ra =
            reinterpret_cast<const unsigned long long*>(W_hh + j0 * HVAL);
        const unsigned long long* rb =
            reinterpret_cast<const unsigned long long*>(W_hh + j1 * HVAL);
        #pragma unroll
        for (int k = 0; k < HVAL / 2; k++) { wA[k] = ra[k]; wB[k] = rb[k]; }
    }
    const float wihA0 = W_ih[2 * j0], wihA1 = W_ih[2 * j0 + 1];
    const float wihB0 = W_ih[2 * j1], wihB1 = W_ih[2 * j1 + 1];
    const float biasA = b_ih[j0] + b_hh[j0];
    const float biasB = b_ih[j1] + b_hh[j1];

    #pragma unroll
    for (int b = 0; b < NB; b++) {
        hbuf[0][lslot + b][j0] = 0.0f;
        hbuf[0][lslot + b][j1] = 0.0f;
    }
    __syncwarp();

    // x streams: one float4 = two timesteps per batch
    const float4* xq[NB];
    float4 cur[NB];
    #pragma unroll
    for (int b = 0; b < NB; b++) {
        xq[b]  = reinterpret_cast<const float4*>(x + (size_t)(gbatch + b) * TVAL * 2);
        cur[b] = xq[b][0];
    }

    // one step: read hbuf[rb], write hbuf[wb]; 4 chains of depth 8 per (row,batch)
    auto do_step = [&](int rb, int wb, const float* xa, const float* xb) {
        unsigned long long acc[NB][2][4];
        #pragma unroll
        for (int b = 0; b < NB; b++) {
            float baseA = fmaf(xa[b], wihA0, fmaf(xb[b], wihA1, biasA));
            float baseB = fmaf(xa[b], wihB0, fmaf(xb[b], wihB1, biasB));
            acc[b][0][0] = pack2(baseA, 0.0f);
            acc[b][1][0] = pack2(baseB, 0.0f);
            acc[b][0][1] = acc[b][0][2] = acc[b][0][3] = 0ull;
            acc[b][1][1] = acc[b][1][2] = acc[b][1][3] = 0ull;
        }
        const ulonglong2* hp[NB];
        #pragma unroll
        for (int b = 0; b < NB; b++)
            hp[b] = reinterpret_cast<const ulonglong2*>(&hbuf[rb][lslot + b][0]);
        #pragma unroll
        for (int kk = 0; kk < HVAL / 4; kk++) {
            const int p = (kk & 1) * 2;        // chain parity: {0,1} vs {2,3}
            #pragma unroll
            for (int b = 0; b < NB; b++) {
                ulonglong2 hv = hp[b][kk];     // LDS.128, warp-broadcast
                acc[b][0][p]     = ffma2(hv.x, wA[2 * kk],     acc[b][0][p]);
                acc[b][0][p + 1] = ffma2(hv.y, wA[2 * kk + 1], acc[b][0][p + 1]);
                acc[b][1][p]     = ffma2(hv.x, wB[2 * kk],     acc[b][1][p]);
                acc[b][1][p + 1] = ffma2(hv.y, wB[2 * kk + 1], acc[b][1][p + 1]);
            }
        }
        #pragma unroll
        for (int b = 0; b < NB; b++) {
            unsigned long long sA = fadd2(fadd2(acc[b][0][0], acc[b][0][1]),
                                          fadd2(acc[b][0][2], acc[b][0][3]));
            unsigned long long sB = fadd2(fadd2(acc[b][1][0], acc[b][1][1]),
                                          fadd2(acc[b][1][2], acc[b][1][3]));
            hbuf[wb][lslot + b][j0] = fast_tanh(lo32(sA) + hi32(sA));
            hbuf[wb][lslot + b][j1] = fast_tanh(lo32(sB) + hi32(sB));
        }
        __syncwarp();
    };

    float xa[NB], xb[NB];
    #pragma unroll 1
    for (int t = 0; t < TVAL; t += 2) {
        int tn = (t + 2 < TVAL) ? (t / 2 + 1) : (TVAL / 2 - 1);
        float4 nxt[NB];
        #pragma unroll
        for (int b = 0; b < NB; b++) nxt[b] = xq[b][tn];

        #pragma unroll
        for (int b = 0; b < NB; b++) { xa[b] = cur[b].x; xb[b] = cur[b].y; }
        do_step(0, 1, xa, xb);
        #pragma unroll
        for (int b = 0; b < NB; b++) { xa[b] = cur[b].z; xb[b] = cur[b].w; }
        do_step(1, 0, xa, xb);

        #pragma unroll
        for (int b = 0; b < NB; b++) cur[b] = nxt[b];
    }

    // Final FC on h_T (hbuf[0] after an even number of steps). O=2 per batch.
    if (lane < 2 * NB) {
        const int which = lane >> 1;
        const int oj    = lane & 1;
        const float* hv  = &hbuf[0][lslot + which][0];
        const float* wfc = W_fc + oj * HVAL;
        float acc = b_fc[oj];
        #pragma unroll
        for (int k = 0; k < HVAL; k++)
            acc = fmaf(hv[k], wfc[k], acc);
        out[(gbatch + which) * 2 + oj] = acc;
    }
}

__global__ void __launch_bounds__(THREADS, 2)
rnn_kernel(const float* __restrict__ x,     // [B,T,2]
           const float* __restrict__ W_ih,  // [64,2]
           const float* __restrict__ W_hh,  // [64,64]
           const float* __restrict__ b_ih,  // [64]
           const float* __restrict__ b_hh,  // [64]
           const float* __restrict__ W_fc,  // [2,64]
           const float* __restrict__ b_fc,  // [2]
           float* __restrict__ out)         // [B,2]
{
    __shared__ __align__(16) float hbuf[2][BTILE][HVAL];

    const int bid  = blockIdx.x;
    const int w    = threadIdx.x >> 5;
    const int lane = threadIdx.x & 31;

    // Batch assignment. CTAs bid and bid+148 land on the same SM
    // (classic bid->smid = LUT[bid % 148]); pair one heavy (8 batches) with
    // one light (6 or 5) so every SM carries 14 or 13 batches (was 16/8).
    int nb, lslot, gbatch;
    if (bid < NSM) {                 // heavy: 4 warps x 2 batches
        nb     = 2;
        lslot  = w * 2;
        gbatch = bid * 8 + lslot;
    } else {                          // light: 6 batches (2,2,1,1) or 5 (2,1,1,1)
        const int l     = bid - NSM;
        const bool six  = (l < 124);
        const int base  = six ? (1184 + l * 6) : (1184 + 744 + (l - 124) * 5);
        // rotate which warps carry 2 batches so SMSP load is spread
        auto nb_of = [&](int ww) {
            int r = (ww + l) & 3;
            return six ? ((r < 2) ? 2 : 1) : ((r == 0) ? 2 : 1);
        };
        int off = 0;
        #pragma unroll
        for (int ww = 0; ww < 4; ww++) if (ww < w) off += nb_of(ww);
        nb     = nb_of(w);
        lslot  = off;
        gbatch = base + off;
    }

    if (nb == 2)
        run_loop<2>(x, W_ih, W_hh, b_ih, b_hh, W_fc, b_fc, out,
                    hbuf, lane, lslot, gbatch);
    else
        run_loop<1>(x, W_ih, W_hh, b_ih, b_hh, W_fc, b_fc, out,
                    hbuf, lane, lslot, gbatch);
}

extern "C" void kernel_launch(void* const* d_in, const int* in_sizes, int n_in,
                              void* d_out, int out_size) {
    const float* x    = (const float*)d_in[0];
    const float* W_ih = (const float*)d_in[1];
    const float* W_hh = (const float*)d_in[2];
    const float* b_ih = (const float*)d_in[3];
    const float* b_hh = (const float*)d_in[4];
    const float* W_fc = (const float*)d_in[5];
    const float* b_fc = (const float*)d_in[6];
    rnn_kernel<<<GRID, THREADS>>>(x, W_ih, W_hh, b_ih, b_hh,
                                  W_fc, b_fc, (float*)d_out);
}